// round 6
// baseline (speedup 1.0000x reference)
#include <cuda_runtime.h>

// x:      (4, 64, 128, 128) fp32  -> 256 independent 128x128 images
// weight: (4, 576, 128, 128) fp32 -> 9 taps per channel, tap k strided by H*W
// steps = 8
//
// Persistent CTAs (1/SM), 512 threads, V=2 (warp owns region rows 2g,2g+1,
// own rows register-resident as packed u64 pairs), fma.rn.f32x2 stencil,
// cp.async.bulk staging prefetched one tile ahead (issue distributed over
// 10 warps). Round 6 deltas vs round 5 (best=62.6us):
//   - rows stored as native u64 pairs: aligned FFMA2 operand pairs are free,
//     accumulators become next state directly (removes ~24 ALU movs/step/thr)
//   - per-step sync via two named producer/consumer barriers split by warp
//     parity (warp g depends only on warps g+-1 = opposite parity), instead
//     of a full-CTA __syncthreads convoy

#define H      128
#define W      128
#define IMG    (H * W)
#define STEPS  8
#define TH     16
#define NT     2048
#define SROWS  34
#define RROWS  32

#define OFF_MBAR 0
#define OFF_BUF  1024
#define OFF_WS   (OFF_BUF + 2 * SROWS * W * 4)   // 1024 + 34816  = 35840
#define OFF_XS   (OFF_WS + 9 * RROWS * W * 4)    // + 147456      = 183296
#define SMEM_TOTAL (OFF_XS + RROWS * W * 4)      // + 16384       = 199680

typedef unsigned long long u64;
typedef unsigned int u32;

__device__ __forceinline__ u32 s2u(const void* p) {
    u32 a;
    asm("{ .reg .u64 t; cvta.to.shared.u64 t, %1; cvt.u32.u64 %0, t; }"
        : "=r"(a) : "l"(p));
    return a;
}
__device__ __forceinline__ u64 pk(float lo, float hi) {
    u64 r; asm("mov.b64 %0, {%1,%2};" : "=l"(r) : "f"(lo), "f"(hi)); return r;
}
__device__ __forceinline__ void upk(u64 v, float& lo, float& hi) {
    asm("mov.b64 {%0,%1}, %2;" : "=f"(lo), "=f"(hi) : "l"(v));
}
__device__ __forceinline__ void fma2(u64& d, u64 a, u64 b) {
    asm("fma.rn.f32x2 %0, %1, %2, %0;" : "+l"(d) : "l"(a), "l"(b));
}
__device__ __forceinline__ float shup(float v) { return __shfl_up_sync(0xffffffffu, v, 1); }
__device__ __forceinline__ float shdn(float v) { return __shfl_down_sync(0xffffffffu, v, 1); }

#define BAR_ARRIVE(id) asm volatile("bar.arrive %0, 512;" :: "n"(id) : "memory")
#define BAR_SYNC(id)   asm volatile("bar.sync %0, 512;"   :: "n"(id) : "memory")

__device__ __forceinline__ void mbar_wait(u32 mbar, u32 parity) {
    asm volatile(
        "{\n\t.reg .pred P;\n\t"
        "W_%=:\n\t"
        "mbarrier.try_wait.parity.shared::cta.b64 P, [%0], %1, 0x989680;\n\t"
        "@P bra.uni D_%=;\n\t"
        "bra.uni W_%=;\n\t"
        "D_%=:\n\t}"
        :: "r"(mbar), "r"(parity) : "memory");
}
__device__ __forceinline__ void bulk_g2s(u32 dst, const void* src, u32 bytes, u32 mbar) {
    asm volatile(
        "cp.async.bulk.shared::cluster.global.mbarrier::complete_tx::bytes "
        "[%0], [%1], %2, [%3];"
        :: "r"(dst), "l"(src), "r"(bytes), "r"(mbar) : "memory");
}

// Distributed prefetch: issuer k (k=0..9) copies one stream (9 weight taps + x).
// mbarrier init count = 10; each issuer does its own arrive.expect_tx.
__device__ __forceinline__ void issue_prefetch_k(int t, int k,
                                                 const float* x, const float* wgt,
                                                 u32 ws, u32 xs, u32 mbar) {
    const int img = t >> 3;
    const int t0  = (t & 7) * TH;
    const int rlo = (t0 - 8 < 0) ? 0 : (t0 - 8);
    const int rhi = (t0 + 24 > H) ? H : (t0 + 24);
    const int nrows = rhi - rlo;
    const int droff = rlo - (t0 - 8);
    const u32 bytes = (u32)nrows * (W * 4);
    asm volatile("mbarrier.arrive.expect_tx.shared.b64 _, [%0], %1;"
                 :: "r"(mbar), "r"(bytes) : "memory");
    if (k < 9) {
        const float* src = wgt + ((size_t)(img * 9 + k) << 14) + rlo * W;
        bulk_g2s(ws + (u32)(k * RROWS + droff) * (W * 4), src, bytes, mbar);
    } else {
        bulk_g2s(xs + (u32)droff * (W * 4), x + ((size_t)img << 14) + rlo * W, bytes, mbar);
    }
}

// From a packed row (a=(x0,x1), b=(x2,x3)) build the 3 misaligned FFMA2
// operand pairs: p0=(xl,x0), p2=(x1,x2), p4=(x3,xr). a and b are used
// directly as the aligned pairs.
__device__ __forceinline__ void rowops(u64 a, u64 b, u64& p0, u64& p2, u64& p4) {
    float x0, x1, x2, x3;
    upk(a, x0, x1); upk(b, x2, x3);            // register renames in SASS
    const float xl = shup(x3), xr = shdn(x0);
    p0 = pk(xl, x0); p2 = pk(x1, x2); p4 = pk(x3, xr);
}

__global__ __launch_bounds__(512, 1)
void diffusion_persist_kernel(const float* __restrict__ x,
                              const float* __restrict__ wgt,
                              float* __restrict__ out)
{
    extern __shared__ char smem[];
    float (*buf)[SROWS][W] = (float (*)[SROWS][W])(smem + OFF_BUF);
    const float* wsp = (const float*)(smem + OFF_WS);
    const float* xsp = (const float*)(smem + OFF_XS);
    const u32 mbar = s2u(smem + OFF_MBAR);
    const u32 ws_a = s2u(smem + OFF_WS);
    const u32 xs_a = s2u(smem + OFF_XS);

    const int tid  = threadIdx.x;
    const int lane = tid & 31;
    const int warp = tid >> 5;          // 0..15; owns region rows 2g, 2g+1
    const int col0 = lane << 2;
    const int g2   = warp * 2;
    const bool evenw  = ((warp & 1) == 0);
    const bool issuer = (lane == 0 && warp < 10);

    // one-time init: guard rows (region rows -1 and 32 -> zero forever), mbar
    if (tid < 128) {
        int b = tid >> 6, r = (tid >> 5) & 1;
        *(float4*)&buf[b][r ? (SROWS - 1) : 0][col0] = make_float4(0.f, 0.f, 0.f, 0.f);
    }
    if (tid == 0) {
        asm volatile("mbarrier.init.shared.b64 [%0], 10;" :: "r"(mbar) : "memory");
    }
    __syncthreads();

    int t = blockIdx.x;
    const int stride = gridDim.x;
    if (issuer && t < NT) issue_prefetch_k(t, warp, x, wgt, ws_a, xs_a, mbar);
    u32 ph = 0;

    for (; t < NT; t += stride) {
        mbar_wait(mbar, ph); ph ^= 1u;

        const int img = t >> 3;
        const int t0  = (t & 7) * TH;

        // ---- tile prologue: weights staging -> normalized packed registers
        u64 Wp[2][3][6];
        u64 y0a, y0b, y1a, y1b;
#pragma unroll
        for (int ro = 0; ro < 2; ro++) {
            const int rr   = g2 + ro;
            const int grow = t0 - 8 + rr;
            const bool rv  = ((unsigned)grow < (unsigned)H);
            float aa[9][4];
            if (rv) {
                float s0 = 0.f, s1 = 0.f, s2 = 0.f, s3 = 0.f;
#pragma unroll
                for (int k = 0; k < 9; k++) {
                    float4 tv = *(const float4*)&wsp[(k * RROWS + rr) * W + col0];
                    aa[k][0] = fabsf(tv.x); aa[k][1] = fabsf(tv.y);
                    aa[k][2] = fabsf(tv.z); aa[k][3] = fabsf(tv.w);
                    s0 += aa[k][0]; s1 += aa[k][1]; s2 += aa[k][2]; s3 += aa[k][3];
                }
                const float i0 = __fdividef(1.f, s0), i1 = __fdividef(1.f, s1);
                const float i2 = __fdividef(1.f, s2), i3 = __fdividef(1.f, s3);
#pragma unroll
                for (int k = 0; k < 9; k++) {
                    aa[k][0] *= i0; aa[k][1] *= i1; aa[k][2] *= i2; aa[k][3] *= i3;
                }
                if (lane == 0)  { aa[0][0] = 0.f; aa[3][0] = 0.f; aa[6][0] = 0.f; }
                if (lane == 31) { aa[2][3] = 0.f; aa[5][3] = 0.f; aa[8][3] = 0.f; }
            } else {
#pragma unroll
                for (int k = 0; k < 9; k++) {
                    aa[k][0] = 0.f; aa[k][1] = 0.f; aa[k][2] = 0.f; aa[k][3] = 0.f;
                }
            }
#pragma unroll
            for (int ki = 0; ki < 3; ki++) {
                Wp[ro][ki][0] = pk(aa[ki * 3 + 0][0], aa[ki * 3 + 0][1]);
                Wp[ro][ki][1] = pk(aa[ki * 3 + 1][0], aa[ki * 3 + 1][1]);
                Wp[ro][ki][2] = pk(aa[ki * 3 + 2][0], aa[ki * 3 + 2][1]);
                Wp[ro][ki][3] = pk(aa[ki * 3 + 0][2], aa[ki * 3 + 0][3]);
                Wp[ro][ki][4] = pk(aa[ki * 3 + 1][2], aa[ki * 3 + 1][3]);
                Wp[ro][ki][5] = pk(aa[ki * 3 + 2][2], aa[ki * 3 + 2][3]);
            }
            // x init (zero outside the image), stored packed
            u64 va_ = 0ull, vb_ = 0ull;
            if (rv) {
                ulonglong2 xv = *(const ulonglong2*)&xsp[rr * W + col0];
                va_ = xv.x; vb_ = xv.y;
            }
            if (ro == 0) { y0a = va_; y0b = vb_; } else { y1a = va_; y1b = vb_; }
            *(ulonglong2*)&buf[0][rr + 1][col0] = make_ulonglong2(va_, vb_);
        }
        __syncthreads();   // staging consumed + buf[0] published (all warps)

        // prefetch next tile (distributed; overlaps the 8-step loop)
        if (issuer && t + stride < NT)
            issue_prefetch_k(t + stride, warp, x, wgt, ws_a, xs_a, mbar);

        // ---- 8 fused steps, parity-split producer/consumer barriers
#pragma unroll
        for (int s = 0; s < STEPS; s++) {
            if (s > 0) {
                // wait for opposite parity's step s-1 publishes
                if (evenw) BAR_SYNC(2); else BAR_SYNC(1);
            }
            const int cb = s & 1;
            ulonglong2 A = *(const ulonglong2*)&buf[cb][g2][col0];      // row 2g-1
            ulonglong2 B = *(const ulonglong2*)&buf[cb][g2 + 3][col0];  // row 2g+2

            u64 pA0, pA2, pA4; rowops(A.x, A.y, pA0, pA2, pA4);
            u64 p00, p02, p04; rowops(y0a, y0b, p00, p02, p04);
            u64 p10, p12, p14; rowops(y1a, y1b, p10, p12, p14);
            u64 pB0, pB2, pB4; rowops(B.x, B.y, pB0, pB2, pB4);

            u64 n0a = 0ull, n0b = 0ull, n1a = 0ull, n1b = 0ull;
            // row above (A) -> out0
            fma2(n0a, Wp[0][0][0], pA0); fma2(n0b, Wp[0][0][3], pA2);
            fma2(n0a, Wp[0][0][1], A.x); fma2(n0b, Wp[0][0][4], A.y);
            fma2(n0a, Wp[0][0][2], pA2); fma2(n0b, Wp[0][0][5], pA4);
            // own row0 -> out0 (center) and out1 (top)
            fma2(n0a, Wp[0][1][0], p00); fma2(n0b, Wp[0][1][3], p02);
            fma2(n1a, Wp[1][0][0], p00); fma2(n1b, Wp[1][0][3], p02);
            fma2(n0a, Wp[0][1][1], y0a); fma2(n0b, Wp[0][1][4], y0b);
            fma2(n1a, Wp[1][0][1], y0a); fma2(n1b, Wp[1][0][4], y0b);
            fma2(n0a, Wp[0][1][2], p02); fma2(n0b, Wp[0][1][5], p04);
            fma2(n1a, Wp[1][0][2], p02); fma2(n1b, Wp[1][0][5], p04);
            // own row1 -> out0 (bottom) and out1 (center)
            fma2(n0a, Wp[0][2][0], p10); fma2(n0b, Wp[0][2][3], p12);
            fma2(n1a, Wp[1][1][0], p10); fma2(n1b, Wp[1][1][3], p12);
            fma2(n0a, Wp[0][2][1], y1a); fma2(n0b, Wp[0][2][4], y1b);
            fma2(n1a, Wp[1][1][1], y1a); fma2(n1b, Wp[1][1][4], y1b);
            fma2(n0a, Wp[0][2][2], p12); fma2(n0b, Wp[0][2][5], p14);
            fma2(n1a, Wp[1][1][2], p12); fma2(n1b, Wp[1][1][5], p14);
            // row below (B) -> out1
            fma2(n1a, Wp[1][2][0], pB0); fma2(n1b, Wp[1][2][3], pB2);
            fma2(n1a, Wp[1][2][1], B.x); fma2(n1b, Wp[1][2][4], B.y);
            fma2(n1a, Wp[1][2][2], pB2); fma2(n1b, Wp[1][2][5], pB4);

            y0a = n0a; y0b = n0b; y1a = n1a; y1b = n1b;

            if (s < STEPS - 1) {
                const int nb = cb ^ 1;
                *(ulonglong2*)&buf[nb][g2 + 1][col0] = make_ulonglong2(y0a, y0b);
                *(ulonglong2*)&buf[nb][g2 + 2][col0] = make_ulonglong2(y1a, y1b);
                // publish-done: release arrive on this parity's barrier
                if (evenw) BAR_ARRIVE(1); else BAR_ARRIVE(2);
            }
        }

        // ---- output: warps 4..11 hold the 16 exact rows (region rows 8..23)
        if ((unsigned)(warp - 4) < 8u) {
            float* ob = out + (size_t)img * IMG + (t0 + g2 - 8) * W + col0;
            *(ulonglong2*)ob       = make_ulonglong2(y0a, y0b);
            *(ulonglong2*)(ob + W) = make_ulonglong2(y1a, y1b);
        }
        // Tile boundary safety: a warp reaches the next prologue only after
        // its step-7 BAR_SYNC, which waited on the arrivals of exactly the
        // warps that read its buf[0] slots at step 6; prologue overwrites
        // buf[0] only. buf reuse within steps follows the same argument.
    }
}

extern "C" void kernel_launch(void* const* d_in, const int* in_sizes, int n_in,
                              void* d_out, int out_size)
{
    const float* x   = (const float*)d_in[0];
    const float* wgt = (const float*)d_in[1];
    float* out       = (float*)d_out;

    int sms = 148;
    cudaDeviceGetAttribute(&sms, cudaDevAttrMultiProcessorCount, 0);
    if (sms < 1) sms = 148;
    if (sms > NT) sms = NT;

    cudaFuncSetAttribute(diffusion_persist_kernel,
                         cudaFuncAttributeMaxDynamicSharedMemorySize, SMEM_TOTAL);
    diffusion_persist_kernel<<<sms, 512, SMEM_TOTAL>>>(x, wgt, out);
}